// round 13
// baseline (speedup 1.0000x reference)
#include <cuda_runtime.h>
#include <math.h>

#define BB   1024
#define TT   512
#define HH   64
#define ROWS 8
#define NTHR 256
#define FTHR 768           // fused kernel threads (3 groups x 256)
#define IPITCH 68          // words per row in h buffers (conflict-free padding)
#define HBUF  (8 * IPITCH) // 544 words per h buffer
#define PPITCH 260         // partial-sum row pitch
#define PBUF  (8 * PPITCH) // 2080 words per partial buffer
#define TCH  16            // t-chunks for pre-GEMM
#define TPC  (TT / TCH)    // 32 timesteps per pre-GEMM CTA
#define LOG2E 1.4426950408889634f

// Scratch (static __device__ arrays are the allowed scratch mechanism)
__device__ float g_pre[(size_t)BB * TT * 256];   // layer-0 x-projection [cta][t][g][r]
__device__ float g_hlast[BB * HH];               // layer-1 final hidden state

__device__ __forceinline__ void fma2(unsigned long long &d,
                                     unsigned long long a, unsigned long long b) {
    asm("fma.rn.f32x2 %0, %1, %2, %0;" : "+l"(d) : "l"(a), "l"(b));
}
__device__ __forceinline__ float2 unpack2(unsigned long long v) {
    float2 f; asm("mov.b64 {%0, %1}, %2;" : "=f"(f.x), "=f"(f.y) : "l"(v)); return f;
}
__device__ __forceinline__ float ex2f(float x) {
    float r; asm("ex2.approx.f32 %0, %1;" : "=f"(r) : "f"(x)); return r;
}
__device__ __forceinline__ float rcpf(float x) {
    float r; asm("rcp.approx.f32 %0, %1;" : "=f"(r) : "f"(x)); return r;
}
__device__ __forceinline__ float fsig(float x) {
    return rcpf(1.0f + ex2f(-LOG2E * x));
}
__device__ __forceinline__ float ftanhf(float x) {
    return fmaf(rcpf(1.0f + ex2f(-2.0f * LOG2E * x)), 2.0f, -1.0f);
}

// ---------------------------------------------------------------------------
// pre0[b][t][g] = b_ih0[g]+b_hh0[g] + x[b][t] @ w_ih0[g]   (time-parallel)
// Unchanged from R10/R12 (best measured: 461us).
// ---------------------------------------------------------------------------
__global__ void __launch_bounds__(NTHR, 1)
gemm_pre(const float* __restrict__ x_in,
         const float* __restrict__ w_ih,
         const float* __restrict__ b_ih, const float* __restrict__ b_hh)
{
    extern __shared__ float sm[];
    float* wq = sm;                  // [16 kk][256 g][4 kp] = 16384 floats (64 KB)
    float* xb = sm + 16384;          // [2 tb][8 rows][IPITCH]

    const int tid = threadIdx.x;
    const int j   = tid >> 2;
    const int rg  = tid & 3;
    const int r0  = rg * 2;
    const int row_base = blockIdx.x * ROWS;
    const int t0 = blockIdx.y * TPC;

    for (int idx = tid; idx < 64 * 256; idx += NTHR) {
        int kp = idx & 3;
        int g  = (idx >> 2) & 255;
        int kk = idx >> 10;
        wq[idx] = w_ih[g * 64 + kk * 4 + kp];
    }

    float bias[4];
    #pragma unroll
    for (int q = 0; q < 4; q++) bias[q] = b_ih[q * 64 + j] + b_hh[q * 64 + j];

    float* outp = g_pre + (size_t)blockIdx.x * TT * 2048;

    for (int it = 0; it < TPC / 2; it++) {
        const int t = t0 + it * 2;
        __syncthreads();
        #pragma unroll
        for (int e = 0; e < 4; e++) {
            int ii = tid + e * 256;
            int tb = ii >> 9, rem = ii & 511;
            int r = rem >> 6, u = rem & 63;
            xb[(tb * 8 + r) * IPITCH + u] =
                x_in[((size_t)(row_base + r) * TT + (t + tb)) * HH + u];
        }
        __syncthreads();

        unsigned long long acc[2][2][4];
        #pragma unroll
        for (int tb = 0; tb < 2; tb++)
            #pragma unroll
            for (int r = 0; r < 2; r++)
                #pragma unroll
                for (int q = 0; q < 4; q++) acc[tb][r][q] = 0ull;

        const float* va  = xb + r0 * IPITCH;
        const float* vb2 = va + IPITCH;
        const float* ua  = xb + (8 + r0) * IPITCH;
        const float* ub  = ua + IPITCH;
        const float* wp  = wq + j * 4;

        #pragma unroll
        for (int kk = 0; kk < 16; kk++) {
            ulonglong2 v0 = *reinterpret_cast<const ulonglong2*>(va  + kk * 4);
            ulonglong2 v1 = *reinterpret_cast<const ulonglong2*>(vb2 + kk * 4);
            ulonglong2 u0 = *reinterpret_cast<const ulonglong2*>(ua  + kk * 4);
            ulonglong2 u1 = *reinterpret_cast<const ulonglong2*>(ub  + kk * 4);
            const float* wc = wp + kk * 1024;
            #pragma unroll
            for (int q = 0; q < 4; q++) {
                ulonglong2 w2 = *reinterpret_cast<const ulonglong2*>(wc + q * 256);
                fma2(acc[0][0][q], v0.x, w2.x);
                fma2(acc[0][0][q], v0.y, w2.y);
                fma2(acc[0][1][q], v1.x, w2.x);
                fma2(acc[0][1][q], v1.y, w2.y);
                fma2(acc[1][0][q], u0.x, w2.x);
                fma2(acc[1][0][q], u0.y, w2.y);
                fma2(acc[1][1][q], u1.x, w2.x);
                fma2(acc[1][1][q], u1.y, w2.y);
            }
        }

        #pragma unroll
        for (int tb = 0; tb < 2; tb++) {
            float* ob = outp + (size_t)(t + tb) * 2048;
            #pragma unroll
            for (int q = 0; q < 4; q++) {
                float2 f0 = unpack2(acc[tb][0][q]);
                float2 f1 = unpack2(acc[tb][1][q]);
                float2 st = make_float2(f0.x + f0.y + bias[q], f1.x + f1.y + bias[q]);
                *reinterpret_cast<float2*>(ob + (q * 64 + j) * 8 + r0) = st;
            }
        }
    }
}

// ---------------------------------------------------------------------------
// Fused 2-layer recurrence, 3-way WARP-SPECIALIZED pipeline (768 threads).
//   G0 (warps 0-7)   @ it: h1(it) = act(pre(it) + h1(it-1)@w_hh0)
//   G1 (warps 8-15)  @ it: partI(it-1) = h1(it-1)@w_ih1  (pure matvec)
//   G2 (warps 16-23) @ it: h2(it-2) = act(bias1 + h2(it-3)@w_hh1 + partI(it-2))
// One barrier per iteration; each group = one 16kk matvec (256 FFMA2/thread).
// Serial activation tails (G0/G2) are staggered and overlap other groups'
// matvec issue. Rings: h1 depth-3, h2 depth-2, partI depth-2.
// ---------------------------------------------------------------------------
__global__ void __launch_bounds__(FTHR, 1)
lstm_fused(const float* __restrict__ w_hh0,
           const float* __restrict__ w_ih1, const float* __restrict__ w_hh1,
           const float* __restrict__ b_ih1, const float* __restrict__ b_hh1)
{
    extern __shared__ float sm[];
    float* wq0  = sm;                 // w_hh0 gate-major, 16384 floats
    float* wq1i = sm + 16384;         // w_ih1 gate-major
    float* wq1h = sm + 32768;         // w_hh1 gate-major
    float* h1b  = sm + 49152;         // [3][8][IPITCH]
    float* h2b  = h1b + 3 * HBUF;     // [2][8][IPITCH]
    float* pIb  = h2b + 2 * HBUF;     // [2][8][PPITCH]

    const int tid = threadIdx.x;
    const int grp = tid >> 8;         // 0, 1, 2
    const int lt  = tid & 255;
    const int j   = lt >> 2;
    const int rg  = lt & 3;
    const int r0  = rg * 2;
    const int row_base = blockIdx.x * ROWS;

    // ---- stage 3 weight tiles gate-major: w[kk*1024 + g*4 + kp]
    for (int idx = tid; idx < 3 * 16384; idx += FTHR) {
        int w  = idx >> 14;
        int e  = idx & 16383;
        int kp = e & 3;
        int g  = (e >> 2) & 255;
        int kk = e >> 10;
        const float* src = (w == 0) ? w_hh0 : (w == 1) ? w_ih1 : w_hh1;
        sm[idx] = src[g * 64 + kk * 4 + kp];
    }
    // init h1(-1) -> h1b slot 2 = 0 ; h2(-1) -> h2b slot 1 = 0
    for (int ii = tid; ii < 2 * 512; ii += FTHR) {
        int half = ii >> 9, rem = ii & 511;
        int r = rem & 7, u = rem >> 3;
        if (half == 0) h1b[2 * HBUF + r * IPITCH + u] = 0.0f;
        else           h2b[1 * HBUF + r * IPITCH + u] = 0.0f;
    }

    float bias1[4];
    #pragma unroll
    for (int q = 0; q < 4; q++) bias1[q] = b_ih1[q * 64 + j] + b_hh1[q * 64 + j];

    const float* prep = g_pre + (size_t)blockIdx.x * TT * 2048;
    float2 pcur[4];
    if (grp == 0) {
        #pragma unroll
        for (int q = 0; q < 4; q++)
            pcur[q] = *reinterpret_cast<const float2*>(prep + (q * 64 + j) * 8 + r0);
    }

    float ca = 0.0f, cb = 0.0f;       // cell states (G0: layer 0, G2: layer 1)
    const float* wp0  = wq0  + j * 4;
    const float* wp1i = wq1i + j * 4;
    const float* wp1h = wq1h + j * 4;

    __syncthreads();

    for (int it = 0; it <= TT + 1; it++) {
        if (grp == 0) {
            if (it < TT) {
                const int t = it;
                // prefetch pre(t+1), clamped
                int tn = (t + 1 < TT) ? (t + 1) : (TT - 1);
                const float* pnb = prep + (size_t)tn * 2048;
                float2 pnext[4];
                #pragma unroll
                for (int q = 0; q < 4; q++)
                    pnext[q] = *reinterpret_cast<const float2*>(pnb + (q * 64 + j) * 8 + r0);

                // acc = h1(t-1) @ w_hh0^T ; h1(t-1) in slot (t+2)%3
                unsigned long long acc[2][4];
                #pragma unroll
                for (int r = 0; r < 2; r++)
                    #pragma unroll
                    for (int q = 0; q < 4; q++) acc[r][q] = 0ull;

                const float* v0p = h1b + ((t + 2) % 3) * HBUF + r0 * IPITCH;
                const float* v1p = v0p + IPITCH;
                #pragma unroll
                for (int kk = 0; kk < 16; kk++) {
                    ulonglong2 v0 = *reinterpret_cast<const ulonglong2*>(v0p + kk * 4);
                    ulonglong2 v1 = *reinterpret_cast<const ulonglong2*>(v1p + kk * 4);
                    const float* wc = wp0 + kk * 1024;
                    #pragma unroll
                    for (int q = 0; q < 4; q++) {
                        ulonglong2 w2 = *reinterpret_cast<const ulonglong2*>(wc + q * 256);
                        fma2(acc[0][q], v0.x, w2.x);
                        fma2(acc[0][q], v0.y, w2.y);
                        fma2(acc[1][q], v1.x, w2.x);
                        fma2(acc[1][q], v1.y, w2.y);
                    }
                }

                float z[2][4];
                #pragma unroll
                for (int q = 0; q < 4; q++) {
                    float2 f0 = unpack2(acc[0][q]);
                    float2 f1 = unpack2(acc[1][q]);
                    z[0][q] = f0.x + f0.y + pcur[q].x;
                    z[1][q] = f1.x + f1.y + pcur[q].y;
                }
                float i0 = fsig(z[0][0]), f0 = fsig(z[0][1]), g0 = ftanhf(z[0][2]), o0 = fsig(z[0][3]);
                float i1 = fsig(z[1][0]), f1 = fsig(z[1][1]), g1 = ftanhf(z[1][2]), o1 = fsig(z[1][3]);
                ca = f0 * ca + i0 * g0;
                cb = f1 * cb + i1 * g1;
                float h0 = o0 * ftanhf(ca);
                float h1 = o1 * ftanhf(cb);
                float* nb = h1b + (t % 3) * HBUF;
                nb[r0 * IPITCH + j]       = h0;
                nb[(r0 + 1) * IPITCH + j] = h1;
                #pragma unroll
                for (int q = 0; q < 4; q++) pcur[q] = pnext[q];
            }
        } else if (grp == 1) {
            if (it >= 1 && it <= TT) {
                const int tm = it - 1;     // partI(tm) = h1(tm) @ w_ih1^T
                unsigned long long acc[2][4];
                #pragma unroll
                for (int r = 0; r < 2; r++)
                    #pragma unroll
                    for (int q = 0; q < 4; q++) acc[r][q] = 0ull;

                const float* v0p = h1b + (tm % 3) * HBUF + r0 * IPITCH;
                const float* v1p = v0p + IPITCH;
                #pragma unroll
                for (int kk = 0; kk < 16; kk++) {
                    ulonglong2 v0 = *reinterpret_cast<const ulonglong2*>(v0p + kk * 4);
                    ulonglong2 v1 = *reinterpret_cast<const ulonglong2*>(v1p + kk * 4);
                    const float* wc = wp1i + kk * 1024;
                    #pragma unroll
                    for (int q = 0; q < 4; q++) {
                        ulonglong2 w2 = *reinterpret_cast<const ulonglong2*>(wc + q * 256);
                        fma2(acc[0][q], v0.x, w2.x);
                        fma2(acc[0][q], v0.y, w2.y);
                        fma2(acc[1][q], v1.x, w2.x);
                        fma2(acc[1][q], v1.y, w2.y);
                    }
                }
                float* pb = pIb + (tm & 1) * PBUF;
                #pragma unroll
                for (int q = 0; q < 4; q++) {
                    float2 f0 = unpack2(acc[0][q]);
                    float2 f1 = unpack2(acc[1][q]);
                    pb[r0 * PPITCH + q * 64 + j]       = f0.x + f0.y;
                    pb[(r0 + 1) * PPITCH + q * 64 + j] = f1.x + f1.y;
                }
            }
        } else {
            if (it >= 2) {
                const int s = it - 2;      // h2(s)
                unsigned long long acc[2][4];
                #pragma unroll
                for (int r = 0; r < 2; r++)
                    #pragma unroll
                    for (int q = 0; q < 4; q++) acc[r][q] = 0ull;

                const float* u0p = h2b + ((s + 1) & 1) * HBUF + r0 * IPITCH;  // h2(s-1)
                const float* u1p = u0p + IPITCH;
                #pragma unroll
                for (int kk = 0; kk < 16; kk++) {
                    ulonglong2 u0 = *reinterpret_cast<const ulonglong2*>(u0p + kk * 4);
                    ulonglong2 u1 = *reinterpret_cast<const ulonglong2*>(u1p + kk * 4);
                    const float* wc = wp1h + kk * 1024;
                    #pragma unroll
                    for (int q = 0; q < 4; q++) {
                        ulonglong2 w2 = *reinterpret_cast<const ulonglong2*>(wc + q * 256);
                        fma2(acc[0][q], u0.x, w2.x);
                        fma2(acc[0][q], u0.y, w2.y);
                        fma2(acc[1][q], u1.x, w2.x);
                        fma2(acc[1][q], u1.y, w2.y);
                    }
                }

                const float* pb = pIb + (s & 1) * PBUF;
                float z[2][4];
                #pragma unroll
                for (int q = 0; q < 4; q++) {
                    float2 f0 = unpack2(acc[0][q]);
                    float2 f1 = unpack2(acc[1][q]);
                    z[0][q] = f0.x + f0.y + pb[r0 * PPITCH + q * 64 + j]       + bias1[q];
                    z[1][q] = f1.x + f1.y + pb[(r0 + 1) * PPITCH + q * 64 + j] + bias1[q];
                }
                float i0 = fsig(z[0][0]), f0 = fsig(z[0][1]), g0 = ftanhf(z[0][2]), o0 = fsig(z[0][3]);
                float i1 = fsig(z[1][0]), f1 = fsig(z[1][1]), g1 = ftanhf(z[1][2]), o1 = fsig(z[1][3]);
                ca = f0 * ca + i0 * g0;
                cb = f1 * cb + i1 * g1;
                float h0 = o0 * ftanhf(ca);
                float h1 = o1 * ftanhf(cb);
                float* nb = h2b + (s & 1) * HBUF;
                nb[r0 * IPITCH + j]       = h0;
                nb[(r0 + 1) * IPITCH + j] = h1;
                if (s == TT - 1) {
                    g_hlast[(row_base + r0) * HH + j]     = h0;
                    g_hlast[(row_base + r0 + 1) * HH + j] = h1;
                }
            }
        }

        __syncthreads();
    }
}

// out[b][o] = softplus(h_last[b] . fc_w[o] + fc_b[o]),  O=32
__global__ void fc_softplus(const float* __restrict__ fc_w,
                            const float* __restrict__ fc_b,
                            float* __restrict__ out)
{
    __shared__ float wsh[64 * 32];
    __shared__ float bsh[32];
    const int tid = threadIdx.x;     // 128 threads

    for (int idx = tid; idx < 64 * 32; idx += 128) {
        int k = idx >> 5, o = idx & 31;
        wsh[idx] = fc_w[o * 64 + k];
    }
    if (tid < 32) bsh[tid] = fc_b[tid];
    __syncthreads();

    int gid = blockIdx.x * 128 + tid;
    int b = gid >> 5, o = gid & 31;
    const float* hr = g_hlast + b * 64;

    float z = bsh[o];
    #pragma unroll
    for (int k = 0; k < 64; k++)
        z += hr[k] * wsh[k * 32 + o];

    float r = (z > 20.0f) ? z : log1pf(__expf(z));
    out[gid] = r;
}

extern "C" void kernel_launch(void* const* d_in, const int* in_sizes, int n_in,
                              void* d_out, int out_size)
{
    (void)in_sizes; (void)n_in; (void)out_size;
    const float* x    = (const float*)d_in[0];
    const float* wih0 = (const float*)d_in[1];
    const float* whh0 = (const float*)d_in[2];
    const float* bih0 = (const float*)d_in[3];
    const float* bhh0 = (const float*)d_in[4];
    const float* wih1 = (const float*)d_in[5];
    const float* whh1 = (const float*)d_in[6];
    const float* bih1 = (const float*)d_in[7];
    const float* bhh1 = (const float*)d_in[8];
    const float* fcw  = (const float*)d_in[9];
    const float* fcb  = (const float*)d_in[10];
    float* out = (float*)d_out;

    const size_t smemA = (size_t)(16384 + 2 * ROWS * IPITCH) * sizeof(float);  // ~69.9 KB
    const size_t smemF = (size_t)(3 * 16384 + 3 * HBUF + 2 * HBUF + 2 * PBUF)
                         * sizeof(float);                                      // 224,128 B
    cudaFuncSetAttribute(gemm_pre,   cudaFuncAttributeMaxDynamicSharedMemorySize, (int)smemA);
    cudaFuncSetAttribute(lstm_fused, cudaFuncAttributeMaxDynamicSharedMemorySize, (int)smemF);

    dim3 pre_grid(BB / ROWS, TCH);

    gemm_pre<<<pre_grid, NTHR, smemA>>>(x, wih0, bih0, bhh0);
    lstm_fused<<<BB / ROWS, FTHR, smemF>>>(whh0, wih1, whh1, bih1, bhh1);
    fc_softplus<<<(BB * 32) / 128, 128>>>(fcw, fcb, out);
}

// round 14
// speedup vs baseline: 1.0876x; 1.0876x over previous
#include <cuda_runtime.h>
#include <math.h>

#define BB   1024
#define TT   512
#define HH   64
#define ROWS 8
#define NTHR 256
#define FTHR 512           // fused kernel threads
#define IPITCH 68          // words per row in h buffers (conflict-free padding)
#define HBUF  (8 * IPITCH) // 544 words per h buffer
#define PPITCH 260         // partial-sum row pitch
#define PBUF  (8 * PPITCH) // 2080 words per partial buffer
#define TCH  16            // t-chunks for pre-GEMM
#define TPC  (TT / TCH)    // 32 timesteps per pre-GEMM CTA
#define LOG2E 1.4426950408889634f

// Scratch (static __device__ arrays are the allowed scratch mechanism)
__device__ float g_pre[(size_t)BB * TT * 256];   // layer-0 x-projection [cta][t][g][r]
__device__ float g_hlast[BB * HH];               // layer-1 final hidden state

__device__ __forceinline__ void fma2(unsigned long long &d,
                                     unsigned long long a, unsigned long long b) {
    asm("fma.rn.f32x2 %0, %1, %2, %0;" : "+l"(d) : "l"(a), "l"(b));
}
__device__ __forceinline__ float2 unpack2(unsigned long long v) {
    float2 f; asm("mov.b64 {%0, %1}, %2;" : "=f"(f.x), "=f"(f.y) : "l"(v)); return f;
}
__device__ __forceinline__ float ex2f(float x) {
    float r; asm("ex2.approx.f32 %0, %1;" : "=f"(r) : "f"(x)); return r;
}
__device__ __forceinline__ float rcpf(float x) {
    float r; asm("rcp.approx.f32 %0, %1;" : "=f"(r) : "f"(x)); return r;
}
__device__ __forceinline__ float fsig(float x) {
    return rcpf(1.0f + ex2f(-LOG2E * x));
}
__device__ __forceinline__ float ftanhf(float x) {
    return fmaf(rcpf(1.0f + ex2f(-2.0f * LOG2E * x)), 2.0f, -1.0f);
}

// ---------------------------------------------------------------------------
// pre0[b][t][g] = b_ih0[g]+b_hh0[g] + x[b][t] @ w_ih0[g]   (time-parallel)
// FOUR timesteps per iteration: per kk, 8 v-LDS + 4 w-LDS feed 64 FFMA2
// (weights amortized over 4t). Inner loop split in two tb-halves to bound
// live registers; __launch_bounds__(256,2) keeps 2 CTAs/SM.
// Output g_pre[cta][t][(q*64+j)*8 + r].
// ---------------------------------------------------------------------------
__global__ void __launch_bounds__(NTHR, 2)
gemm_pre(const float* __restrict__ x_in,
         const float* __restrict__ w_ih,
         const float* __restrict__ b_ih, const float* __restrict__ b_hh)
{
    extern __shared__ float sm[];
    float* wq = sm;                  // [16 kk][256 g][4 kp] = 16384 floats (64 KB)
    float* xb = sm + 16384;          // [4 tb][8 rows][IPITCH]

    const int tid = threadIdx.x;
    const int j   = tid >> 2;
    const int rg  = tid & 3;
    const int r0  = rg * 2;
    const int row_base = blockIdx.x * ROWS;
    const int t0 = blockIdx.y * TPC;

    for (int idx = tid; idx < 64 * 256; idx += NTHR) {
        int kp = idx & 3;
        int g  = (idx >> 2) & 255;
        int kk = idx >> 10;
        wq[idx] = w_ih[g * 64 + kk * 4 + kp];
    }

    float bias[4];
    #pragma unroll
    for (int q = 0; q < 4; q++) bias[q] = b_ih[q * 64 + j] + b_hh[q * 64 + j];

    float* outp = g_pre + (size_t)blockIdx.x * TT * 2048;

    for (int it = 0; it < TPC / 4; it++) {
        const int t = t0 + it * 4;
        __syncthreads();
        // load 4 timestep-tiles (4 x 8 x 64 = 2048 elems, 8 per thread)
        #pragma unroll
        for (int e = 0; e < 8; e++) {
            int ii = tid + e * 256;
            int tb = ii >> 9, rem = ii & 511;
            int r = rem >> 6, u = rem & 63;
            xb[(tb * 8 + r) * IPITCH + u] =
                x_in[((size_t)(row_base + r) * TT + (t + tb)) * HH + u];
        }
        __syncthreads();

        unsigned long long acc[4][2][4];   // [tb][row][q]
        #pragma unroll
        for (int tb = 0; tb < 4; tb++)
            #pragma unroll
            for (int r = 0; r < 2; r++)
                #pragma unroll
                for (int q = 0; q < 4; q++) acc[tb][r][q] = 0ull;

        const float* wp = wq + j * 4;

        #pragma unroll
        for (int kk = 0; kk < 16; kk++) {
            const float* wc = wp + kk * 1024;
            // preload the 4 weight vectors for this kk (shared across 4 tb)
            ulonglong2 w2[4];
            #pragma unroll
            for (int q = 0; q < 4; q++)
                w2[q] = *reinterpret_cast<const ulonglong2*>(wc + q * 256);

            // tb-half 0: tiles 0,1
            #pragma unroll
            for (int tb = 0; tb < 2; tb++) {
                const float* va = xb + (tb * 8 + r0) * IPITCH + kk * 4;
                ulonglong2 v0 = *reinterpret_cast<const ulonglong2*>(va);
                ulonglong2 v1 = *reinterpret_cast<const ulonglong2*>(va + IPITCH);
                #pragma unroll
                for (int q = 0; q < 4; q++) {
                    fma2(acc[tb][0][q], v0.x, w2[q].x);
                    fma2(acc[tb][0][q], v0.y, w2[q].y);
                    fma2(acc[tb][1][q], v1.x, w2[q].x);
                    fma2(acc[tb][1][q], v1.y, w2[q].y);
                }
            }
            // tb-half 1: tiles 2,3
            #pragma unroll
            for (int tb = 2; tb < 4; tb++) {
                const float* va = xb + (tb * 8 + r0) * IPITCH + kk * 4;
                ulonglong2 v0 = *reinterpret_cast<const ulonglong2*>(va);
                ulonglong2 v1 = *reinterpret_cast<const ulonglong2*>(va + IPITCH);
                #pragma unroll
                for (int q = 0; q < 4; q++) {
                    fma2(acc[tb][0][q], v0.x, w2[q].x);
                    fma2(acc[tb][0][q], v0.y, w2[q].y);
                    fma2(acc[tb][1][q], v1.x, w2[q].x);
                    fma2(acc[tb][1][q], v1.y, w2[q].y);
                }
            }
        }

        #pragma unroll
        for (int tb = 0; tb < 4; tb++) {
            float* ob = outp + (size_t)(t + tb) * 2048;
            #pragma unroll
            for (int q = 0; q < 4; q++) {
                float2 f0 = unpack2(acc[tb][0][q]);
                float2 f1 = unpack2(acc[tb][1][q]);
                float2 st = make_float2(f0.x + f0.y + bias[q], f1.x + f1.y + bias[q]);
                *reinterpret_cast<float2*>(ob + (q * 64 + j) * 8 + r0) = st;
            }
        }
    }
}

// ---------------------------------------------------------------------------
// Fused 2-layer recurrence, BALANCED software pipeline (512 threads).
// EXACT R12 structure (best measured fused: ~1700us).
//   Group A (warps 0-7) at iteration it:
//     h1(it) = act(pre(it) + h1(it-1) @ w_hh0)                [16 kk]
//     partA(it-1) = h1(it-1) @ w_ih1[:, 0:32]  (reuses A's v loads) [8 kk]
//   Group B (warps 8-15) at iteration it (s = it-2):
//     h2(s) = act(bias1 + h2(s-1)@w_hh1 [16kk] + h1(s)@w_ih1[:,32:64] [8kk]
//             + partA(s))
//   Both groups: 384 FFMA2/thread/iter; ONE barrier per iteration.
//   h1 ring depth 3 (mod 3); h2 and partA depth 2.
// ---------------------------------------------------------------------------
__global__ void __launch_bounds__(FTHR, 1)
lstm_fused(const float* __restrict__ w_hh0,
           const float* __restrict__ w_ih1, const float* __restrict__ w_hh1,
           const float* __restrict__ b_ih1, const float* __restrict__ b_hh1)
{
    extern __shared__ float sm[];
    float* wq0  = sm;                 // w_hh0 gate-major, 16384 floats
    float* wq1i = sm + 16384;         // w_ih1 gate-major
    float* wq1h = sm + 32768;         // w_hh1 gate-major
    float* h1b  = sm + 49152;         // [3][8][IPITCH]
    float* h2b  = h1b + 3 * HBUF;     // [2][8][IPITCH]
    float* pAb  = h2b + 2 * HBUF;     // [2][8][PPITCH]

    const int tid = threadIdx.x;
    const int lt  = tid & 255;
    const bool gA = tid < 256;
    const int j   = lt >> 2;
    const int rg  = lt & 3;
    const int r0  = rg * 2;
    const int row_base = blockIdx.x * ROWS;

    // ---- stage 3 weight tiles gate-major: w[kk*1024 + g*4 + kp]
    for (int idx = tid; idx < 3 * 16384; idx += FTHR) {
        int w  = idx >> 14;
        int e  = idx & 16383;
        int kp = e & 3;
        int g  = (e >> 2) & 255;
        int kk = e >> 10;
        const float* src = (w == 0) ? w_hh0 : (w == 1) ? w_ih1 : w_hh1;
        sm[idx] = src[g * 64 + kk * 4 + kp];
    }
    // init h1(-1) -> h1b buf 2 = 0 ; h2(-1) -> h2b buf 1 = 0
    for (int ii = tid; ii < 2 * 512; ii += FTHR) {
        int half = ii >> 9, rem = ii & 511;
        int r = rem & 7, u = rem >> 3;
        if (half == 0) h1b[2 * HBUF + r * IPITCH + u] = 0.0f;
        else           h2b[1 * HBUF + r * IPITCH + u] = 0.0f;
    }

    float bias1[4];
    #pragma unroll
    for (int q = 0; q < 4; q++) bias1[q] = b_ih1[q * 64 + j] + b_hh1[q * 64 + j];

    const float* prep = g_pre + (size_t)blockIdx.x * TT * 2048;
    float2 pcur[4];
    if (gA) {
        #pragma unroll
        for (int q = 0; q < 4; q++)
            pcur[q] = *reinterpret_cast<const float2*>(prep + (q * 64 + j) * 8 + r0);
    }

    float ca = 0.0f, cb = 0.0f;       // cell states (A: layer 0, B: layer 1)
    const float* wp0  = wq0  + j * 4;
    const float* wp1i = wq1i + j * 4;
    const float* wp1h = wq1h + j * 4;

    __syncthreads();

    for (int it = 0; it <= TT + 1; it++) {
        if (gA) {
            if (it <= TT) {
                const int t = it;
                // prefetch pre(t+1), clamped
                float2 pnext[4];
                if (t < TT) {
                    int tn = (t + 1 < TT) ? (t + 1) : (TT - 1);
                    const float* pnb = prep + (size_t)tn * 2048;
                    #pragma unroll
                    for (int q = 0; q < 4; q++)
                        pnext[q] = *reinterpret_cast<const float2*>(pnb + (q * 64 + j) * 8 + r0);
                }

                // v = h1(t-1) in h1b[(t+2)%3]
                unsigned long long acc0[2][4], accP[2][4];
                #pragma unroll
                for (int r = 0; r < 2; r++)
                    #pragma unroll
                    for (int q = 0; q < 4; q++) { acc0[r][q] = 0ull; accP[r][q] = 0ull; }

                const float* v0p = h1b + ((t + 2) % 3) * HBUF + r0 * IPITCH;
                const float* v1p = v0p + IPITCH;
                #pragma unroll
                for (int kk = 0; kk < 16; kk++) {
                    ulonglong2 v0 = *reinterpret_cast<const ulonglong2*>(v0p + kk * 4);
                    ulonglong2 v1 = *reinterpret_cast<const ulonglong2*>(v1p + kk * 4);
                    const float* wc = wp0 + kk * 1024;
                    #pragma unroll
                    for (int q = 0; q < 4; q++) {
                        ulonglong2 w2 = *reinterpret_cast<const ulonglong2*>(wc + q * 256);
                        fma2(acc0[0][q], v0.x, w2.x);
                        fma2(acc0[0][q], v0.y, w2.y);
                        fma2(acc0[1][q], v1.x, w2.x);
                        fma2(acc0[1][q], v1.y, w2.y);
                    }
                    if (kk < 8) {   // partA(t-1): w_ih1 columns k<32, SAME v
                        const float* wci = wp1i + kk * 1024;
                        #pragma unroll
                        for (int q = 0; q < 4; q++) {
                            ulonglong2 wi = *reinterpret_cast<const ulonglong2*>(wci + q * 256);
                            fma2(accP[0][q], v0.x, wi.x);
                            fma2(accP[0][q], v0.y, wi.y);
                            fma2(accP[1][q], v1.x, wi.x);
                            fma2(accP[1][q], v1.y, wi.y);
                        }
                    }
                }

                // h1(t) update
                if (t < TT) {
                    float z[2][4];
                    #pragma unroll
                    for (int q = 0; q < 4; q++) {
                        float2 f0 = unpack2(acc0[0][q]);
                        float2 f1 = unpack2(acc0[1][q]);
                        z[0][q] = f0.x + f0.y + pcur[q].x;
                        z[1][q] = f1.x + f1.y + pcur[q].y;
                    }
                    float i0 = fsig(z[0][0]), f0 = fsig(z[0][1]), g0 = ftanhf(z[0][2]), o0 = fsig(z[0][3]);
                    float i1 = fsig(z[1][0]), f1 = fsig(z[1][1]), g1 = ftanhf(z[1][2]), o1 = fsig(z[1][3]);
                    ca = f0 * ca + i0 * g0;
                    cb = f1 * cb + i1 * g1;
                    float h0 = o0 * ftanhf(ca);
                    float h1 = o1 * ftanhf(cb);
                    float* nb = h1b + (t % 3) * HBUF;
                    nb[r0 * IPITCH + j]       = h0;
                    nb[(r0 + 1) * IPITCH + j] = h1;
                    #pragma unroll
                    for (int q = 0; q < 4; q++) pcur[q] = pnext[q];
                }
                // publish partA(t-1)
                if (t >= 1) {
                    float* pb = pAb + ((t - 1) & 1) * PBUF;
                    #pragma unroll
                    for (int q = 0; q < 4; q++) {
                        float2 f0 = unpack2(accP[0][q]);
                        float2 f1 = unpack2(accP[1][q]);
                        pb[r0 * PPITCH + q * 64 + j]       = f0.x + f0.y;
                        pb[(r0 + 1) * PPITCH + q * 64 + j] = f1.x + f1.y;
                    }
                }
            }
        } else {
            if (it >= 2) {
                const int s = it - 2;   // computing h2(s)
                unsigned long long acc[2][4];
                #pragma unroll
                for (int r = 0; r < 2; r++)
                    #pragma unroll
                    for (int q = 0; q < 4; q++) acc[r][q] = 0ull;

                const float* u0p = h2b + ((s + 1) & 1) * HBUF + r0 * IPITCH;  // h2(s-1)
                const float* u1p = u0p + IPITCH;
                const float* v0p = h1b + (s % 3) * HBUF + r0 * IPITCH;        // h1(s)
                const float* v1p = v0p + IPITCH;
                #pragma unroll
                for (int kk = 0; kk < 16; kk++) {
                    ulonglong2 u0 = *reinterpret_cast<const ulonglong2*>(u0p + kk * 4);
                    ulonglong2 u1 = *reinterpret_cast<const ulonglong2*>(u1p + kk * 4);
                    const float* wcH = wp1h + kk * 1024;
                    #pragma unroll
                    for (int q = 0; q < 4; q++) {
                        ulonglong2 wH = *reinterpret_cast<const ulonglong2*>(wcH + q * 256);
                        fma2(acc[0][q], u0.x, wH.x);
                        fma2(acc[0][q], u0.y, wH.y);
                        fma2(acc[1][q], u1.x, wH.x);
                        fma2(acc[1][q], u1.y, wH.y);
                    }
                    if (kk >= 8) {  // h1(s) @ w_ih1[:, 32:64]
                        ulonglong2 v0 = *reinterpret_cast<const ulonglong2*>(v0p + kk * 4);
                        ulonglong2 v1 = *reinterpret_cast<const ulonglong2*>(v1p + kk * 4);
                        const float* wcI = wp1i + kk * 1024;
                        #pragma unroll
                        for (int q = 0; q < 4; q++) {
                            ulonglong2 wI = *reinterpret_cast<const ulonglong2*>(wcI + q * 256);
                            fma2(acc[0][q], v0.x, wI.x);
                            fma2(acc[0][q], v0.y, wI.y);
                            fma2(acc[1][q], v1.x, wI.x);
                            fma2(acc[1][q], v1.y, wI.y);
                        }
                    }
                }

                // add partA(s) + bias, activate, update h2(s)
                const float* pb = pAb + (s & 1) * PBUF;
                float z[2][4];
                #pragma unroll
                for (int q = 0; q < 4; q++) {
                    float2 f0 = unpack2(acc[0][q]);
                    float2 f1 = unpack2(acc[1][q]);
                    z[0][q] = f0.x + f0.y + pb[r0 * PPITCH + q * 64 + j]       + bias1[q];
                    z[1][q] = f1.x + f1.y + pb[(r0 + 1) * PPITCH + q * 64 + j] + bias1[q];
                }
                float i0 = fsig(z[0][0]), f0 = fsig(z[0][1]), g0 = ftanhf(z[0][2]), o0 = fsig(z[0][3]);
                float i1 = fsig(z[1][0]), f1 = fsig(z[1][1]), g1 = ftanhf(z[1][2]), o1 = fsig(z[1][3]);
                ca = f0 * ca + i0 * g0;
                cb = f1 * cb + i1 * g1;
                float h0 = o0 * ftanhf(ca);
                float h1 = o1 * ftanhf(cb);
                float* nb = h2b + (s & 1) * HBUF;
                nb[r0 * IPITCH + j]       = h0;
                nb[(r0 + 1) * IPITCH + j] = h1;
                if (s == TT - 1) {
                    g_hlast[(row_base + r0) * HH + j]     = h0;
                    g_hlast[(row_base + r0 + 1) * HH + j] = h1;
                }
            }
        }

        __syncthreads();
    }
}

// out[b][o] = softplus(h_last[b] . fc_w[o] + fc_b[o]),  O=32
__global__ void fc_softplus(const float* __restrict__ fc_w,
                            const float* __restrict__ fc_b,
                            float* __restrict__ out)
{
    __shared__ float wsh[64 * 32];
    __shared__ float bsh[32];
    const int tid = threadIdx.x;     // 128 threads

    for (int idx = tid; idx < 64 * 32; idx += 128) {
        int k = idx >> 5, o = idx & 31;
        wsh[idx] = fc_w[o * 64 + k];
    }
    if (tid < 32) bsh[tid] = fc_b[tid];
    __syncthreads();

    int gid = blockIdx.x * 128 + tid;
    int b = gid >> 5, o = gid & 31;
    const float* hr = g_hlast + b * 64;

    float z = bsh[o];
    #pragma unroll
    for (int k = 0; k < 64; k++)
        z += hr[k] * wsh[k * 32 + o];

    float r = (z > 20.0f) ? z : log1pf(__expf(z));
    out[gid] = r;
}

extern "C" void kernel_launch(void* const* d_in, const int* in_sizes, int n_in,
                              void* d_out, int out_size)
{
    (void)in_sizes; (void)n_in; (void)out_size;
    const float* x    = (const float*)d_in[0];
    const float* wih0 = (const float*)d_in[1];
    const float* whh0 = (const float*)d_in[2];
    const float* bih0 = (const float*)d_in[3];
    const float* bhh0 = (const float*)d_in[4];
    const float* wih1 = (const float*)d_in[5];
    const float* whh1 = (const float*)d_in[6];
    const float* bih1 = (const float*)d_in[7];
    const float* bhh1 = (const float*)d_in[8];
    const float* fcw  = (const float*)d_in[9];
    const float* fcb  = (const float*)d_in[10];
    float* out = (float*)d_out;

    const size_t smemA = (size_t)(16384 + 4 * ROWS * IPITCH) * sizeof(float);  // ~74.2 KB
    const size_t smemF = (size_t)(3 * 16384 + 3 * HBUF + 2 * HBUF + 2 * PBUF)
                         * sizeof(float);                                      // 224,128 B
    cudaFuncSetAttribute(gemm_pre,   cudaFuncAttributeMaxDynamicSharedMemorySize, (int)smemA);
    cudaFuncSetAttribute(lstm_fused, cudaFuncAttributeMaxDynamicSharedMemorySize, (int)smemF);

    dim3 pre_grid(BB / ROWS, TCH);

    gemm_pre<<<pre_grid, NTHR, smemA>>>(x, wih0, bih0, bhh0);
    lstm_fused<<<BB / ROWS, FTHR, smemF>>>(whh0, wih1, whh1, bih1, bhh1);
    fc_softplus<<<(BB * 32) / 128, 128>>>(fcw, fcb, out);
}

// round 15
// speedup vs baseline: 1.1117x; 1.0221x over previous
#include <cuda_runtime.h>
#include <math.h>

#define BB   1024
#define TT   512
#define HH   64
#define ROWS 8
#define NTHR 256
#define FTHR 512           // fused kernel threads
#define IPITCH 68          // words per row in h buffers (conflict-free padding)
#define HBUF  (8 * IPITCH) // 544 words per h buffer
#define PASLOT 2048        // compact partA slot: 256 threads x 8 floats
#define TCH  16            // t-chunks for pre-GEMM
#define TPC  (TT / TCH)    // 32 timesteps per pre-GEMM CTA
#define LOG2E 1.4426950408889634f

// Scratch (static __device__ arrays are the allowed scratch mechanism)
__device__ float g_pre[(size_t)BB * TT * 256];   // layer-0 x-projection [cta][t][g][r]
__device__ float g_hlast[BB * HH];               // layer-1 final hidden state

__device__ __forceinline__ void fma2(unsigned long long &d,
                                     unsigned long long a, unsigned long long b) {
    asm("fma.rn.f32x2 %0, %1, %2, %0;" : "+l"(d) : "l"(a), "l"(b));
}
__device__ __forceinline__ float2 unpack2(unsigned long long v) {
    float2 f; asm("mov.b64 {%0, %1}, %2;" : "=f"(f.x), "=f"(f.y) : "l"(v)); return f;
}
__device__ __forceinline__ float ex2f(float x) {
    float r; asm("ex2.approx.f32 %0, %1;" : "=f"(r) : "f"(x)); return r;
}
__device__ __forceinline__ float rcpf(float x) {
    float r; asm("rcp.approx.f32 %0, %1;" : "=f"(r) : "f"(x)); return r;
}
__device__ __forceinline__ float fsig(float x) {
    return rcpf(1.0f + ex2f(-LOG2E * x));
}
__device__ __forceinline__ float ftanhf(float x) {
    return fmaf(rcpf(1.0f + ex2f(-2.0f * LOG2E * x)), 2.0f, -1.0f);
}
__device__ __forceinline__ float sum2(unsigned long long v) {
    float2 f = unpack2(v); return f.x + f.y;
}

// ---------------------------------------------------------------------------
// pre0[b][t][g] = b_ih0[g]+b_hh0[g] + x[b][t] @ w_ih0[g]   (time-parallel)
// R14 version (measured 427us): FOUR timesteps per iteration.
// ---------------------------------------------------------------------------
__global__ void __launch_bounds__(NTHR, 2)
gemm_pre(const float* __restrict__ x_in,
         const float* __restrict__ w_ih,
         const float* __restrict__ b_ih, const float* __restrict__ b_hh)
{
    extern __shared__ float sm[];
    float* wq = sm;                  // [16 kk][256 g][4 kp] = 16384 floats (64 KB)
    float* xb = sm + 16384;          // [4 tb][8 rows][IPITCH]

    const int tid = threadIdx.x;
    const int j   = tid >> 2;
    const int rg  = tid & 3;
    const int r0  = rg * 2;
    const int row_base = blockIdx.x * ROWS;
    const int t0 = blockIdx.y * TPC;

    for (int idx = tid; idx < 64 * 256; idx += NTHR) {
        int kp = idx & 3;
        int g  = (idx >> 2) & 255;
        int kk = idx >> 10;
        wq[idx] = w_ih[g * 64 + kk * 4 + kp];
    }

    float bias[4];
    #pragma unroll
    for (int q = 0; q < 4; q++) bias[q] = b_ih[q * 64 + j] + b_hh[q * 64 + j];

    float* outp = g_pre + (size_t)blockIdx.x * TT * 2048;

    for (int it = 0; it < TPC / 4; it++) {
        const int t = t0 + it * 4;
        __syncthreads();
        #pragma unroll
        for (int e = 0; e < 8; e++) {
            int ii = tid + e * 256;
            int tb = ii >> 9, rem = ii & 511;
            int r = rem >> 6, u = rem & 63;
            xb[(tb * 8 + r) * IPITCH + u] =
                x_in[((size_t)(row_base + r) * TT + (t + tb)) * HH + u];
        }
        __syncthreads();

        unsigned long long acc[4][2][4];   // [tb][row][q]
        #pragma unroll
        for (int tb = 0; tb < 4; tb++)
            #pragma unroll
            for (int r = 0; r < 2; r++)
                #pragma unroll
                for (int q = 0; q < 4; q++) acc[tb][r][q] = 0ull;

        const float* wp = wq + j * 4;

        #pragma unroll
        for (int kk = 0; kk < 16; kk++) {
            const float* wc = wp + kk * 1024;
            ulonglong2 w2[4];
            #pragma unroll
            for (int q = 0; q < 4; q++)
                w2[q] = *reinterpret_cast<const ulonglong2*>(wc + q * 256);

            #pragma unroll
            for (int tb = 0; tb < 2; tb++) {
                const float* va = xb + (tb * 8 + r0) * IPITCH + kk * 4;
                ulonglong2 v0 = *reinterpret_cast<const ulonglong2*>(va);
                ulonglong2 v1 = *reinterpret_cast<const ulonglong2*>(va + IPITCH);
                #pragma unroll
                for (int q = 0; q < 4; q++) {
                    fma2(acc[tb][0][q], v0.x, w2[q].x);
                    fma2(acc[tb][0][q], v0.y, w2[q].y);
                    fma2(acc[tb][1][q], v1.x, w2[q].x);
                    fma2(acc[tb][1][q], v1.y, w2[q].y);
                }
            }
            #pragma unroll
            for (int tb = 2; tb < 4; tb++) {
                const float* va = xb + (tb * 8 + r0) * IPITCH + kk * 4;
                ulonglong2 v0 = *reinterpret_cast<const ulonglong2*>(va);
                ulonglong2 v1 = *reinterpret_cast<const ulonglong2*>(va + IPITCH);
                #pragma unroll
                for (int q = 0; q < 4; q++) {
                    fma2(acc[tb][0][q], v0.x, w2[q].x);
                    fma2(acc[tb][0][q], v0.y, w2[q].y);
                    fma2(acc[tb][1][q], v1.x, w2[q].x);
                    fma2(acc[tb][1][q], v1.y, w2[q].y);
                }
            }
        }

        #pragma unroll
        for (int tb = 0; tb < 4; tb++) {
            float* ob = outp + (size_t)(t + tb) * 2048;
            #pragma unroll
            for (int q = 0; q < 4; q++) {
                float2 f0 = unpack2(acc[tb][0][q]);
                float2 f1 = unpack2(acc[tb][1][q]);
                float2 st = make_float2(f0.x + f0.y + bias[q], f1.x + f1.y + bias[q]);
                *reinterpret_cast<float2*>(ob + (q * 64 + j) * 8 + r0) = st;
            }
        }
    }
}

// ---------------------------------------------------------------------------
// Fused 2-layer recurrence, DECOUPLED producer-consumer pipeline (512 thr).
// Dependency is one-directional (A: layer0 + partA, B: layer1 consumer), so
// the full __syncthreads lock-step is replaced by named barriers:
//   bar1 (256): A-internal write->read ordering (every A iteration)
//   bar2 (256): B-internal read->write ordering (single h2 buffer)
//   bar3 (512): A arrives (end of t), B syncs (top of it): B@it waits A@it-1
//   bar4 (512): B arrives (end of it), A syncs from t>=4: A leads by <= 2
// Rings: h1 depth 4, partA depth 3 (compact thread-symmetric layout),
// h2 single buffer. Race audit in commit message.
// ---------------------------------------------------------------------------
__global__ void __launch_bounds__(FTHR, 1)
lstm_fused(const float* __restrict__ w_hh0,
           const float* __restrict__ w_ih1, const float* __restrict__ w_hh1,
           const float* __restrict__ b_ih1, const float* __restrict__ b_hh1)
{
    extern __shared__ float sm[];
    float* wq0  = sm;                 // w_hh0 gate-major, 16384 floats
    float* wq1i = sm + 16384;         // w_ih1 gate-major
    float* wq1h = sm + 32768;         // w_hh1 gate-major
    float* h1b  = sm + 49152;         // [4][8][IPITCH]
    float* h2b  = h1b + 4 * HBUF;     // [8][IPITCH] (single buffer)
    float* pAb  = h2b + HBUF;         // [3][PASLOT] compact partA

    const int tid = threadIdx.x;
    const int lt  = tid & 255;
    const bool gA = tid < 256;
    const int j   = lt >> 2;
    const int rg  = lt & 3;
    const int r0  = rg * 2;
    const int row_base = blockIdx.x * ROWS;

    // ---- stage 3 weight tiles gate-major: w[kk*1024 + g*4 + kp]
    for (int idx = tid; idx < 3 * 16384; idx += FTHR) {
        int w  = idx >> 14;
        int e  = idx & 16383;
        int kp = e & 3;
        int g  = (e >> 2) & 255;
        int kk = e >> 10;
        const float* src = (w == 0) ? w_hh0 : (w == 1) ? w_ih1 : w_hh1;
        sm[idx] = src[g * 64 + kk * 4 + kp];
    }
    // init h1(-1) -> h1b slot 3 = 0 ; h2(-1) -> h2b = 0
    for (int ii = tid; ii < 2 * 512; ii += FTHR) {
        int half = ii >> 9, rem = ii & 511;
        int r = rem & 7, u = rem >> 3;
        if (half == 0) h1b[3 * HBUF + r * IPITCH + u] = 0.0f;
        else           h2b[r * IPITCH + u] = 0.0f;
    }

    float bias1[4];
    #pragma unroll
    for (int q = 0; q < 4; q++) bias1[q] = b_ih1[q * 64 + j] + b_hh1[q * 64 + j];

    const float* prep = g_pre + (size_t)blockIdx.x * TT * 2048;
    float2 pcur[4];
    if (gA) {
        #pragma unroll
        for (int q = 0; q < 4; q++)
            pcur[q] = *reinterpret_cast<const float2*>(prep + (q * 64 + j) * 8 + r0);
    }

    float ca = 0.0f, cb = 0.0f;
    const float* wp0  = wq0  + j * 4;
    const float* wp1i = wq1i + j * 4;
    const float* wp1h = wq1h + j * 4;

    __syncthreads();

    if (gA) {
        // ================= GROUP A: layer 0 + partA producer =================
        for (int t = 0; t <= TT; t++) {
            if (t >= 4) asm volatile("bar.sync 4, 512;" ::: "memory");

            // prefetch pre(t+1)
            float2 pnext[4];
            if (t < TT) {
                int tn = (t + 1 < TT) ? (t + 1) : (TT - 1);
                const float* pnb = prep + (size_t)tn * 2048;
                #pragma unroll
                for (int q = 0; q < 4; q++)
                    pnext[q] = *reinterpret_cast<const float2*>(pnb + (q * 64 + j) * 8 + r0);
            }

            // matvec on h1(t-1), slot (t+3)&3
            unsigned long long acc0[2][4], accP[2][4];
            #pragma unroll
            for (int r = 0; r < 2; r++)
                #pragma unroll
                for (int q = 0; q < 4; q++) { acc0[r][q] = 0ull; accP[r][q] = 0ull; }

            const float* v0p = h1b + ((t + 3) & 3) * HBUF + r0 * IPITCH;
            const float* v1p = v0p + IPITCH;
            #pragma unroll
            for (int kk = 0; kk < 16; kk++) {
                ulonglong2 v0 = *reinterpret_cast<const ulonglong2*>(v0p + kk * 4);
                ulonglong2 v1 = *reinterpret_cast<const ulonglong2*>(v1p + kk * 4);
                const float* wc = wp0 + kk * 1024;
                #pragma unroll
                for (int q = 0; q < 4; q++) {
                    ulonglong2 w2 = *reinterpret_cast<const ulonglong2*>(wc + q * 256);
                    fma2(acc0[0][q], v0.x, w2.x);
                    fma2(acc0[0][q], v0.y, w2.y);
                    fma2(acc0[1][q], v1.x, w2.x);
                    fma2(acc0[1][q], v1.y, w2.y);
                }
                if (kk < 8) {   // partA(t-1): w_ih1 columns k<32, SAME v
                    const float* wci = wp1i + kk * 1024;
                    #pragma unroll
                    for (int q = 0; q < 4; q++) {
                        ulonglong2 wi = *reinterpret_cast<const ulonglong2*>(wci + q * 256);
                        fma2(accP[0][q], v0.x, wi.x);
                        fma2(accP[0][q], v0.y, wi.y);
                        fma2(accP[1][q], v1.x, wi.x);
                        fma2(accP[1][q], v1.y, wi.y);
                    }
                }
            }

            // h1(t) update -> slot t&3
            if (t < TT) {
                float z[2][4];
                #pragma unroll
                for (int q = 0; q < 4; q++) {
                    z[0][q] = sum2(acc0[0][q]) + pcur[q].x;
                    z[1][q] = sum2(acc0[1][q]) + pcur[q].y;
                }
                float i0 = fsig(z[0][0]), f0 = fsig(z[0][1]), g0 = ftanhf(z[0][2]), o0 = fsig(z[0][3]);
                float i1 = fsig(z[1][0]), f1 = fsig(z[1][1]), g1 = ftanhf(z[1][2]), o1 = fsig(z[1][3]);
                ca = f0 * ca + i0 * g0;
                cb = f1 * cb + i1 * g1;
                float h0 = o0 * ftanhf(ca);
                float h1 = o1 * ftanhf(cb);
                float* nb = h1b + (t & 3) * HBUF;
                nb[r0 * IPITCH + j]       = h0;
                nb[(r0 + 1) * IPITCH + j] = h1;
                #pragma unroll
                for (int q = 0; q < 4; q++) pcur[q] = pnext[q];
            }
            // publish partA(t-1) -> compact slot (t-1)%3
            if (t >= 1) {
                float* pw = pAb + ((t - 1) % 3) * PASLOT + lt * 8;
                float4 w0, w1;
                w0.x = sum2(accP[0][0]); w0.y = sum2(accP[0][1]);
                w0.z = sum2(accP[0][2]); w0.w = sum2(accP[0][3]);
                w1.x = sum2(accP[1][0]); w1.y = sum2(accP[1][1]);
                w1.z = sum2(accP[1][2]); w1.w = sum2(accP[1][3]);
                *reinterpret_cast<float4*>(pw)     = w0;
                *reinterpret_cast<float4*>(pw + 4) = w1;
            }

            asm volatile("bar.sync 1, 256;" ::: "memory");   // A-internal + STS drain
            asm volatile("bar.arrive 3, 512;" ::: "memory"); // signal B: iter t done
        }
    } else {
        // ================= GROUP B: layer 1 consumer =================
        for (int it = 1; it <= TT + 1; it++) {
            asm volatile("bar.sync 3, 512;" ::: "memory");   // wait A finished it-1
            if (it >= 2) {
                const int s = it - 2;   // computing h2(s)
                unsigned long long acc[2][4];
                #pragma unroll
                for (int r = 0; r < 2; r++)
                    #pragma unroll
                    for (int q = 0; q < 4; q++) acc[r][q] = 0ull;

                const float* u0p = h2b + r0 * IPITCH;                   // h2(s-1)
                const float* u1p = u0p + IPITCH;
                const float* v0p = h1b + (s & 3) * HBUF + r0 * IPITCH;  // h1(s)
                const float* v1p = v0p + IPITCH;
                #pragma unroll
                for (int kk = 0; kk < 16; kk++) {
                    ulonglong2 u0 = *reinterpret_cast<const ulonglong2*>(u0p + kk * 4);
                    ulonglong2 u1 = *reinterpret_cast<const ulonglong2*>(u1p + kk * 4);
                    const float* wcH = wp1h + kk * 1024;
                    #pragma unroll
                    for (int q = 0; q < 4; q++) {
                        ulonglong2 wH = *reinterpret_cast<const ulonglong2*>(wcH + q * 256);
                        fma2(acc[0][q], u0.x, wH.x);
                        fma2(acc[0][q], u0.y, wH.y);
                        fma2(acc[1][q], u1.x, wH.x);
                        fma2(acc[1][q], u1.y, wH.y);
                    }
                    if (kk >= 8) {  // h1(s) @ w_ih1[:, 32:64]
                        ulonglong2 v0 = *reinterpret_cast<const ulonglong2*>(v0p + kk * 4);
                        ulonglong2 v1 = *reinterpret_cast<const ulonglong2*>(v1p + kk * 4);
                        const float* wcI = wp1i + kk * 1024;
                        #pragma unroll
                        for (int q = 0; q < 4; q++) {
                            ulonglong2 wI = *reinterpret_cast<const ulonglong2*>(wcI + q * 256);
                            fma2(acc[0][q], v0.x, wI.x);
                            fma2(acc[0][q], v0.y, wI.y);
                            fma2(acc[1][q], v1.x, wI.x);
                            fma2(acc[1][q], v1.y, wI.y);
                        }
                    }
                }

                // all B threads finished reading h2(s-1) before overwriting
                asm volatile("bar.sync 2, 256;" ::: "memory");

                // partA(s) from compact slot s%3 + bias, activate, write h2(s)
                const float* pr = pAb + (s % 3) * PASLOT + lt * 8;
                float4 pa0 = *reinterpret_cast<const float4*>(pr);
                float4 pa1 = *reinterpret_cast<const float4*>(pr + 4);

                float z00 = sum2(acc[0][0]) + pa0.x + bias1[0];
                float z01 = sum2(acc[0][1]) + pa0.y + bias1[1];
                float z02 = sum2(acc[0][2]) + pa0.z + bias1[2];
                float z03 = sum2(acc[0][3]) + pa0.w + bias1[3];
                float z10 = sum2(acc[1][0]) + pa1.x + bias1[0];
                float z11 = sum2(acc[1][1]) + pa1.y + bias1[1];
                float z12 = sum2(acc[1][2]) + pa1.z + bias1[2];
                float z13 = sum2(acc[1][3]) + pa1.w + bias1[3];

                float i0 = fsig(z00), f0 = fsig(z01), g0 = ftanhf(z02), o0 = fsig(z03);
                float i1 = fsig(z10), f1 = fsig(z11), g1 = ftanhf(z12), o1 = fsig(z13);
                ca = f0 * ca + i0 * g0;
                cb = f1 * cb + i1 * g1;
                float h0 = o0 * ftanhf(ca);
                float h1 = o1 * ftanhf(cb);
                h2b[r0 * IPITCH + j]       = h0;
                h2b[(r0 + 1) * IPITCH + j] = h1;
                if (s == TT - 1) {
                    g_hlast[(row_base + r0) * HH + j]     = h0;
                    g_hlast[(row_base + r0 + 1) * HH + j] = h1;
                }

                asm volatile("bar.arrive 4, 512;" ::: "memory"); // backpressure release
            }
        }
    }
}

// out[b][o] = softplus(h_last[b] . fc_w[o] + fc_b[o]),  O=32
__global__ void fc_softplus(const float* __restrict__ fc_w,
                            const float* __restrict__ fc_b,
                            float* __restrict__ out)
{
    __shared__ float wsh[64 * 32];
    __shared__ float bsh[32];
    const int tid = threadIdx.x;     // 128 threads

    for (int idx = tid; idx < 64 * 32; idx += 128) {
        int k = idx >> 5, o = idx & 31;
        wsh[idx] = fc_w[o * 64 + k];
    }
    if (tid < 32) bsh[tid] = fc_b[tid];
    __syncthreads();

    int gid = blockIdx.x * 128 + tid;
    int b = gid >> 5, o = gid & 31;
    const float* hr = g_hlast + b * 64;

    float z = bsh[o];
    #pragma unroll
    for (int k = 0; k < 64; k++)
        z += hr[k] * wsh[k * 32 + o];

    float r = (z > 20.0f) ? z : log1pf(__expf(z));
    out[gid] = r;
}

extern "C" void kernel_launch(void* const* d_in, const int* in_sizes, int n_in,
                              void* d_out, int out_size)
{
    (void)in_sizes; (void)n_in; (void)out_size;
    const float* x    = (const float*)d_in[0];
    const float* wih0 = (const float*)d_in[1];
    const float* whh0 = (const float*)d_in[2];
    const float* bih0 = (const float*)d_in[3];
    const float* bhh0 = (const float*)d_in[4];
    const float* wih1 = (const float*)d_in[5];
    const float* whh1 = (const float*)d_in[6];
    const float* bih1 = (const float*)d_in[7];
    const float* bhh1 = (const float*)d_in[8];
    const float* fcw  = (const float*)d_in[9];
    const float* fcb  = (const float*)d_in[10];
    float* out = (float*)d_out;

    const size_t smemA = (size_t)(16384 + 4 * ROWS * IPITCH) * sizeof(float);  // ~74.2 KB
    const size_t smemF = (size_t)(3 * 16384 + 4 * HBUF + HBUF + 3 * PASLOT)
                         * sizeof(float);                                      // 232,064 B
    cudaFuncSetAttribute(gemm_pre,   cudaFuncAttributeMaxDynamicSharedMemorySize, (int)smemA);
    cudaFuncSetAttribute(lstm_fused, cudaFuncAttributeMaxDynamicSharedMemorySize, (int)smemF);

    dim3 pre_grid(BB / ROWS, TCH);

    gemm_pre<<<pre_grid, NTHR, smemA>>>(x, wih0, bih0, bhh0);
    lstm_fused<<<BB / ROWS, FTHR, smemF>>>(whh0, wih1, whh1, bih1, bhh1);
    fc_softplus<<<(BB * 32) / 128, 128>>>(fcw, fcb, out);
}

// round 16
// speedup vs baseline: 1.1473x; 1.0321x over previous
#include <cuda_runtime.h>
#include <math.h>

#define BB   1024
#define TT   512
#define HH   64
#define ROWS 8
#define NTHR 256
#define FTHR 512           // fused kernel threads
#define IPITCH 68          // words per row in h buffers (conflict-free padding)
#define HBUF  (8 * IPITCH) // 544 words per h buffer
#define PPITCH 260         // partial-sum row pitch
#define PBUF  (8 * PPITCH) // 2080 words per partial buffer
#define TCH  16            // t-chunks for pre-GEMM
#define TPC  (TT / TCH)    // 32 timesteps per pre-GEMM CTA
#define LOG2E 1.4426950408889634f

// Scratch (static __device__ arrays are the allowed scratch mechanism)
__device__ float g_pre[(size_t)BB * TT * 256];   // layer-0 x-projection [cta][t][g][r]
__device__ float g_hlast[BB * HH];               // layer-1 final hidden state

__device__ __forceinline__ void fma2(unsigned long long &d,
                                     unsigned long long a, unsigned long long b) {
    asm("fma.rn.f32x2 %0, %1, %2, %0;" : "+l"(d) : "l"(a), "l"(b));
}
__device__ __forceinline__ float2 unpack2(unsigned long long v) {
    float2 f; asm("mov.b64 {%0, %1}, %2;" : "=f"(f.x), "=f"(f.y) : "l"(v)); return f;
}
__device__ __forceinline__ float ex2f(float x) {
    float r; asm("ex2.approx.f32 %0, %1;" : "=f"(r) : "f"(x)); return r;
}
__device__ __forceinline__ float rcpf(float x) {
    float r; asm("rcp.approx.f32 %0, %1;" : "=f"(r) : "f"(x)); return r;
}
__device__ __forceinline__ float fsig(float x) {
    return rcpf(1.0f + ex2f(-LOG2E * x));
}
__device__ __forceinline__ float ftanhf(float x) {
    return fmaf(rcpf(1.0f + ex2f(-2.0f * LOG2E * x)), 2.0f, -1.0f);
}

// ---------------------------------------------------------------------------
// pre0[b][t][g] = b_ih0[g]+b_hh0[g] + x[b][t] @ w_ih0[g]   (time-parallel)
// R14/R15 version (best measured 406us): FOUR timesteps per iteration,
// per kk 8 v-LDS + 4 w-LDS feed 64 FFMA2; __launch_bounds__(256,2).
// ---------------------------------------------------------------------------
__global__ void __launch_bounds__(NTHR, 2)
gemm_pre(const float* __restrict__ x_in,
         const float* __restrict__ w_ih,
         const float* __restrict__ b_ih, const float* __restrict__ b_hh)
{
    extern __shared__ float sm[];
    float* wq = sm;                  // [16 kk][256 g][4 kp] = 16384 floats (64 KB)
    float* xb = sm + 16384;          // [4 tb][8 rows][IPITCH]

    const int tid = threadIdx.x;
    const int j   = tid >> 2;
    const int rg  = tid & 3;
    const int r0  = rg * 2;
    const int row_base = blockIdx.x * ROWS;
    const int t0 = blockIdx.y * TPC;

    for (int idx = tid; idx < 64 * 256; idx += NTHR) {
        int kp = idx & 3;
        int g  = (idx >> 2) & 255;
        int kk = idx >> 10;
        wq[idx] = w_ih[g * 64 + kk * 4 + kp];
    }

    float bias[4];
    #pragma unroll
    for (int q = 0; q < 4; q++) bias[q] = b_ih[q * 64 + j] + b_hh[q * 64 + j];

    float* outp = g_pre + (size_t)blockIdx.x * TT * 2048;

    for (int it = 0; it < TPC / 4; it++) {
        const int t = t0 + it * 4;
        __syncthreads();
        #pragma unroll
        for (int e = 0; e < 8; e++) {
            int ii = tid + e * 256;
            int tb = ii >> 9, rem = ii & 511;
            int r = rem >> 6, u = rem & 63;
            xb[(tb * 8 + r) * IPITCH + u] =
                x_in[((size_t)(row_base + r) * TT + (t + tb)) * HH + u];
        }
        __syncthreads();

        unsigned long long acc[4][2][4];   // [tb][row][q]
        #pragma unroll
        for (int tb = 0; tb < 4; tb++)
            #pragma unroll
            for (int r = 0; r < 2; r++)
                #pragma unroll
                for (int q = 0; q < 4; q++) acc[tb][r][q] = 0ull;

        const float* wp = wq + j * 4;

        #pragma unroll
        for (int kk = 0; kk < 16; kk++) {
            const float* wc = wp + kk * 1024;
            ulonglong2 w2[4];
            #pragma unroll
            for (int q = 0; q < 4; q++)
                w2[q] = *reinterpret_cast<const ulonglong2*>(wc + q * 256);

            #pragma unroll
            for (int tb = 0; tb < 2; tb++) {
                const float* va = xb + (tb * 8 + r0) * IPITCH + kk * 4;
                ulonglong2 v0 = *reinterpret_cast<const ulonglong2*>(va);
                ulonglong2 v1 = *reinterpret_cast<const ulonglong2*>(va + IPITCH);
                #pragma unroll
                for (int q = 0; q < 4; q++) {
                    fma2(acc[tb][0][q], v0.x, w2[q].x);
                    fma2(acc[tb][0][q], v0.y, w2[q].y);
                    fma2(acc[tb][1][q], v1.x, w2[q].x);
                    fma2(acc[tb][1][q], v1.y, w2[q].y);
                }
            }
            #pragma unroll
            for (int tb = 2; tb < 4; tb++) {
                const float* va = xb + (tb * 8 + r0) * IPITCH + kk * 4;
                ulonglong2 v0 = *reinterpret_cast<const ulonglong2*>(va);
                ulonglong2 v1 = *reinterpret_cast<const ulonglong2*>(va + IPITCH);
                #pragma unroll
                for (int q = 0; q < 4; q++) {
                    fma2(acc[tb][0][q], v0.x, w2[q].x);
                    fma2(acc[tb][0][q], v0.y, w2[q].y);
                    fma2(acc[tb][1][q], v1.x, w2[q].x);
                    fma2(acc[tb][1][q], v1.y, w2[q].y);
                }
            }
        }

        #pragma unroll
        for (int tb = 0; tb < 4; tb++) {
            float* ob = outp + (size_t)(t + tb) * 2048;
            #pragma unroll
            for (int q = 0; q < 4; q++) {
                float2 f0 = unpack2(acc[tb][0][q]);
                float2 f1 = unpack2(acc[tb][1][q]);
                float2 st = make_float2(f0.x + f0.y + bias[q], f1.x + f1.y + bias[q]);
                *reinterpret_cast<float2*>(ob + (q * 64 + j) * 8 + r0) = st;
            }
        }
    }
}

// ---------------------------------------------------------------------------
// Fused 2-layer recurrence, BALANCED software pipeline (512 threads).
// EXACT R12 structure (best measured fused: ~1706us).
//   Group A (warps 0-7) at iteration it:
//     h1(it) = act(pre(it) + h1(it-1) @ w_hh0)                [16 kk]
//     partA(it-1) = h1(it-1) @ w_ih1[:, 0:32]  (reuses A's v loads) [8 kk]
//   Group B (warps 8-15) at iteration it (s = it-2):
//     h2(s) = act(bias1 + h2(s-1)@w_hh1 [16kk] + h1(s)@w_ih1[:,32:64] [8kk]
//             + partA(s))
//   Both groups: 384 FFMA2/thread/iter; ONE barrier per iteration.
//   h1 ring depth 3 (mod 3); h2 and partA depth 2.
// ---------------------------------------------------------------------------
__global__ void __launch_bounds__(FTHR, 1)
lstm_fused(const float* __restrict__ w_hh0,
           const float* __restrict__ w_ih1, const float* __restrict__ w_hh1,
           const float* __restrict__ b_ih1, const float* __restrict__ b_hh1)
{
    extern __shared__ float sm[];
    float* wq0  = sm;                 // w_hh0 gate-major, 16384 floats
    float* wq1i = sm + 16384;         // w_ih1 gate-major
    float* wq1h = sm + 32768;         // w_hh1 gate-major
    float* h1b  = sm + 49152;         // [3][8][IPITCH]
    float* h2b  = h1b + 3 * HBUF;     // [2][8][IPITCH]
    float* pAb  = h2b + 2 * HBUF;     // [2][8][PPITCH]

    const int tid = threadIdx.x;
    const int lt  = tid & 255;
    const bool gA = tid < 256;
    const int j   = lt >> 2;
    const int rg  = lt & 3;
    const int r0  = rg * 2;
    const int row_base = blockIdx.x * ROWS;

    // ---- stage 3 weight tiles gate-major: w[kk*1024 + g*4 + kp]
    for (int idx = tid; idx < 3 * 16384; idx += FTHR) {
        int w  = idx >> 14;
        int e  = idx & 16383;
        int kp = e & 3;
        int g  = (e >> 2) & 255;
        int kk = e >> 10;
        const float* src = (w == 0) ? w_hh0 : (w == 1) ? w_ih1 : w_hh1;
        sm[idx] = src[g * 64 + kk * 4 + kp];
    }
    // init h1(-1) -> h1b buf 2 = 0 ; h2(-1) -> h2b buf 1 = 0
    for (int ii = tid; ii < 2 * 512; ii += FTHR) {
        int half = ii >> 9, rem = ii & 511;
        int r = rem & 7, u = rem >> 3;
        if (half == 0) h1b[2 * HBUF + r * IPITCH + u] = 0.0f;
        else           h2b[1 * HBUF + r * IPITCH + u] = 0.0f;
    }

    float bias1[4];
    #pragma unroll
    for (int q = 0; q < 4; q++) bias1[q] = b_ih1[q * 64 + j] + b_hh1[q * 64 + j];

    const float* prep = g_pre + (size_t)blockIdx.x * TT * 2048;
    float2 pcur[4];
    if (gA) {
        #pragma unroll
        for (int q = 0; q < 4; q++)
            pcur[q] = *reinterpret_cast<const float2*>(prep + (q * 64 + j) * 8 + r0);
    }

    float ca = 0.0f, cb = 0.0f;       // cell states (A: layer 0, B: layer 1)
    const float* wp0  = wq0  + j * 4;
    const float* wp1i = wq1i + j * 4;
    const float* wp1h = wq1h + j * 4;

    __syncthreads();

    for (int it = 0; it <= TT + 1; it++) {
        if (gA) {
            if (it <= TT) {
                const int t = it;
                // prefetch pre(t+1), clamped
                float2 pnext[4];
                if (t < TT) {
                    int tn = (t + 1 < TT) ? (t + 1) : (TT - 1);
                    const float* pnb = prep + (size_t)tn * 2048;
                    #pragma unroll
                    for (int q = 0; q < 4; q++)
                        pnext[q] = *reinterpret_cast<const float2*>(pnb + (q * 64 + j) * 8 + r0);
                }

                // v = h1(t-1) in h1b[(t+2)%3]
                unsigned long long acc0[2][4], accP[2][4];
                #pragma unroll
                for (int r = 0; r < 2; r++)
                    #pragma unroll
                    for (int q = 0; q < 4; q++) { acc0[r][q] = 0ull; accP[r][q] = 0ull; }

                const float* v0p = h1b + ((t + 2) % 3) * HBUF + r0 * IPITCH;
                const float* v1p = v0p + IPITCH;
                #pragma unroll
                for (int kk = 0; kk < 16; kk++) {
                    ulonglong2 v0 = *reinterpret_cast<const ulonglong2*>(v0p + kk * 4);
                    ulonglong2 v1 = *reinterpret_cast<const ulonglong2*>(v1p + kk * 4);
                    const float* wc = wp0 + kk * 1024;
                    #pragma unroll
                    for (int q = 0; q < 4; q++) {
                        ulonglong2 w2 = *reinterpret_cast<const ulonglong2*>(wc + q * 256);
                        fma2(acc0[0][q], v0.x, w2.x);
                        fma2(acc0[0][q], v0.y, w2.y);
                        fma2(acc0[1][q], v1.x, w2.x);
                        fma2(acc0[1][q], v1.y, w2.y);
                    }
                    if (kk < 8) {   // partA(t-1): w_ih1 columns k<32, SAME v
                        const float* wci = wp1i + kk * 1024;
                        #pragma unroll
                        for (int q = 0; q < 4; q++) {
                            ulonglong2 wi = *reinterpret_cast<const ulonglong2*>(wci + q * 256);
                            fma2(accP[0][q], v0.x, wi.x);
                            fma2(accP[0][q], v0.y, wi.y);
                            fma2(accP[1][q], v1.x, wi.x);
                            fma2(accP[1][q], v1.y, wi.y);
                        }
                    }
                }

                // h1(t) update
                if (t < TT) {
                    float z[2][4];
                    #pragma unroll
                    for (int q = 0; q < 4; q++) {
                        float2 f0 = unpack2(acc0[0][q]);
                        float2 f1 = unpack2(acc0[1][q]);
                        z[0][q] = f0.x + f0.y + pcur[q].x;
                        z[1][q] = f1.x + f1.y + pcur[q].y;
                    }
                    float i0 = fsig(z[0][0]), f0 = fsig(z[0][1]), g0 = ftanhf(z[0][2]), o0 = fsig(z[0][3]);
                    float i1 = fsig(z[1][0]), f1 = fsig(z[1][1]), g1 = ftanhf(z[1][2]), o1 = fsig(z[1][3]);
                    ca = f0 * ca + i0 * g0;
                    cb = f1 * cb + i1 * g1;
                    float h0 = o0 * ftanhf(ca);
                    float h1 = o1 * ftanhf(cb);
                    float* nb = h1b + (t % 3) * HBUF;
                    nb[r0 * IPITCH + j]       = h0;
                    nb[(r0 + 1) * IPITCH + j] = h1;
                    #pragma unroll
                    for (int q = 0; q < 4; q++) pcur[q] = pnext[q];
                }
                // publish partA(t-1)
                if (t >= 1) {
                    float* pb = pAb + ((t - 1) & 1) * PBUF;
                    #pragma unroll
                    for (int q = 0; q < 4; q++) {
                        float2 f0 = unpack2(accP[0][q]);
                        float2 f1 = unpack2(accP[1][q]);
                        pb[r0 * PPITCH + q * 64 + j]       = f0.x + f0.y;
                        pb[(r0 + 1) * PPITCH + q * 64 + j] = f1.x + f1.y;
                    }
                }
            }
        } else {
            if (it >= 2) {
                const int s = it - 2;   // computing h2(s)
                unsigned long long acc[2][4];
                #pragma unroll
                for (int r = 0; r < 2; r++)
                    #pragma unroll
                    for (int q = 0; q < 4; q++) acc[r][q] = 0ull;

                const float* u0p = h2b + ((s + 1) & 1) * HBUF + r0 * IPITCH;  // h2(s-1)
                const float* u1p = u0p + IPITCH;
                const float* v0p = h1b + (s % 3) * HBUF + r0 * IPITCH;        // h1(s)
                const float* v1p = v0p + IPITCH;
                #pragma unroll
                for (int kk = 0; kk < 16; kk++) {
                    ulonglong2 u0 = *reinterpret_cast<const ulonglong2*>(u0p + kk * 4);
                    ulonglong2 u1 = *reinterpret_cast<const ulonglong2*>(u1p + kk * 4);
                    const float* wcH = wp1h + kk * 1024;
                    #pragma unroll
                    for (int q = 0; q < 4; q++) {
                        ulonglong2 wH = *reinterpret_cast<const ulonglong2*>(wcH + q * 256);
                        fma2(acc[0][q], u0.x, wH.x);
                        fma2(acc[0][q], u0.y, wH.y);
                        fma2(acc[1][q], u1.x, wH.x);
                        fma2(acc[1][q], u1.y, wH.y);
                    }
                    if (kk >= 8) {  // h1(s) @ w_ih1[:, 32:64]
                        ulonglong2 v0 = *reinterpret_cast<const ulonglong2*>(v0p + kk * 4);
                        ulonglong2 v1 = *reinterpret_cast<const ulonglong2*>(v1p + kk * 4);
                        const float* wcI = wp1i + kk * 1024;
                        #pragma unroll
                        for (int q = 0; q < 4; q++) {
                            ulonglong2 wI = *reinterpret_cast<const ulonglong2*>(wcI + q * 256);
                            fma2(acc[0][q], v0.x, wI.x);
                            fma2(acc[0][q], v0.y, wI.y);
                            fma2(acc[1][q], v1.x, wI.x);
                            fma2(acc[1][q], v1.y, wI.y);
                        }
                    }
                }

                // add partA(s) + bias, activate, update h2(s)
                const float* pb = pAb + (s & 1) * PBUF;
                float z[2][4];
                #pragma unroll
                for (int q = 0; q < 4; q++) {
                    float2 f0 = unpack2(acc[0][q]);
                    float2 f1 = unpack2(acc[1][q]);
                    z[0][q] = f0.x + f0.y + pb[r0 * PPITCH + q * 64 + j]       + bias1[q];
                    z[1][q] = f1.x + f1.y + pb[(r0 + 1) * PPITCH + q * 64 + j] + bias1[q];
                }
                float i0 = fsig(z[0][0]), f0 = fsig(z[0][1]), g0 = ftanhf(z[0][2]), o0 = fsig(z[0][3]);
                float i1 = fsig(z[1][0]), f1 = fsig(z[1][1]), g1 = ftanhf(z[1][2]), o1 = fsig(z[1][3]);
                ca = f0 * ca + i0 * g0;
                cb = f1 * cb + i1 * g1;
                float h0 = o0 * ftanhf(ca);
                float h1 = o1 * ftanhf(cb);
                float* nb = h2b + (s & 1) * HBUF;
                nb[r0 * IPITCH + j]       = h0;
                nb[(r0 + 1) * IPITCH + j] = h1;
                if (s == TT - 1) {
                    g_hlast[(row_base + r0) * HH + j]     = h0;
                    g_hlast[(row_base + r0 + 1) * HH + j] = h1;
                }
            }
        }

        __syncthreads();
    }
}

// out[b][o] = softplus(h_last[b] . fc_w[o] + fc_b[o]),  O=32
__global__ void fc_softplus(const float* __restrict__ fc_w,
                            const float* __restrict__ fc_b,
                            float* __restrict__ out)
{
    __shared__ float wsh[64 * 32];
    __shared__ float bsh[32];
    const int tid = threadIdx.x;     // 128 threads

    for (int idx = tid; idx < 64 * 32; idx += 128) {
        int k = idx >> 5, o = idx & 31;
        wsh[idx] = fc_w[o * 64 + k];
    }
    if (tid < 32) bsh[tid] = fc_b[tid];
    __syncthreads();

    int gid = blockIdx.x * 128 + tid;
    int b = gid >> 5, o = gid & 31;
    const float* hr = g_hlast + b * 64;

    float z = bsh[o];
    #pragma unroll
    for (int k = 0; k < 64; k++)
        z += hr[k] * wsh[k * 32 + o];

    float r = (z > 20.0f) ? z : log1pf(__expf(z));
    out[gid] = r;
}

extern "C" void kernel_launch(void* const* d_in, const int* in_sizes, int n_in,
                              void* d_out, int out_size)
{
    (void)in_sizes; (void)n_in; (void)out_size;
    const float* x    = (const float*)d_in[0];
    const float* wih0 = (const float*)d_in[1];
    const float* whh0 = (const float*)d_in[2];
    const float* bih0 = (const float*)d_in[3];
    const float* bhh0 = (const float*)d_in[4];
    const float* wih1 = (const float*)d_in[5];
    const float* whh1 = (const float*)d_in[6];
    const float* bih1 = (const float*)d_in[7];
    const float* bhh1 = (const float*)d_in[8];
    const float* fcw  = (const float*)d_in[9];
    const float* fcb  = (const float*)d_in[10];
    float* out = (float*)d_out;

    const size_t smemA = (size_t)(16384 + 4 * ROWS * IPITCH) * sizeof(float);  // ~74.2 KB
    const size_t smemF = (size_t)(3 * 16384 + 3 * HBUF + 2 * HBUF + 2 * PBUF)
                         * sizeof(float);                                      // 224,128 B
    cudaFuncSetAttribute(gemm_pre,   cudaFuncAttributeMaxDynamicSharedMemorySize, (int)smemA);
    cudaFuncSetAttribute(lstm_fused, cudaFuncAttributeMaxDynamicSharedMemorySize, (int)smemF);

    dim3 pre_grid(BB / ROWS, TCH);

    gemm_pre<<<pre_grid, NTHR, smemA>>>(x, wih0, bih0, bhh0);
    lstm_fused<<<BB / ROWS, FTHR, smemF>>>(whh0, wih1, whh1, bih1, bhh1);
    fc_softplus<<<(BB * 32) / 128, 128>>>(fcw, fcb, out);
}